// round 3
// baseline (speedup 1.0000x reference)
#include <cuda_runtime.h>
#include <math.h>
#include <limits.h>

#define Nn 30000
#define Ee 400000
#define C1n 15000
#define E2n 100000
#define C2n 7500
#define Bn 16

typedef unsigned long long ull;

// ---------------- scratch (device globals) -----------------------------------
__device__ int   g_deg1[Nn],  g_off1[Nn + 1],  g_cur1[Nn];
__device__ int   g_degD1[Nn], g_offD1[Nn + 1], g_curD1[Nn];
__device__ int   g_deg2[C1n],  g_off2[C1n + 1],  g_cur2[C1n];
__device__ int   g_degD2[C1n], g_offD2[C1n + 1], g_curD2[C1n];
__device__ int   g_csr1[Ee], g_posD1[Ee];
__device__ int   g_csr2[E2n], g_posD2[E2n];
__device__ int   g_cntc1[C1n];
__device__ int   g_tsum[90], g_tcar[90];
__device__ __align__(16) float g_buf1[(size_t)Ee * 32];
__device__ __align__(16) float g_buf2[(size_t)E2n * 64];   // ull pairs {m0,m1}
__device__ float g_xp[C1n * 32];
__device__ float g_possum[C1n * 3];
__device__ int   g_batchp[C1n];
__device__ float g_maxabs;
__device__ __align__(16) float g_G2[(size_t)C1n * 1600];   // pairs (c,c+32) at 2c,2c+1
__device__ __align__(16) float g_bb2[C1n * 64];            // pairs (c,c+32)
__device__ float g_x3[C2n * 64];
__device__ int   g_batch2[C2n];
__device__ float g_gsum[Bn * 64];
__device__ float g_gcnt[Bn];

__device__ __forceinline__ void atomicMaxFloat(float* addr, float val) {
    if (val >= 0.f) atomicMax((int*)addr, __float_as_int(val));
    else            atomicMin((unsigned int*)addr, __float_as_uint(val));
}
__device__ __forceinline__ float elu1(float v) { return v > 0.f ? v : expm1f(v); }

__device__ __forceinline__ ull fma2(ull a, ull b, ull c) {
    ull d;
    asm("fma.rn.f32x2 %0, %1, %2, %3;" : "=l"(d) : "l"(a), "l"(b), "l"(c));
    return d;
}
__device__ __forceinline__ ull pack2f(float a, float b) {
    ull r;
    asm("mov.b64 %0, {%1, %2};" : "=l"(r) : "f"(a), "f"(b));
    return r;
}
__device__ __forceinline__ void unpack2f(float& a, float& b, ull v) {
    asm("mov.b64 {%0, %1}, %2;" : "=f"(a), "=f"(b) : "l"(v));
}

// ---------------- K0: init ----------------------------------------------------
__global__ void k_init() {
    int t = blockIdx.x * blockDim.x + threadIdx.x;
    int S = gridDim.x * blockDim.x;
    const float NEGINF = __int_as_float(0xff800000);
    for (int i = t; i < Nn; i += S) { g_deg1[i] = 0; g_degD1[i] = 0; }
    for (int i = t; i < C1n; i += S) { g_deg2[i] = 0; g_degD2[i] = 0; g_cntc1[i] = 0; g_batchp[i] = INT_MIN; }
    for (int i = t; i < C1n * 32; i += S) g_xp[i] = NEGINF;
    for (int i = t; i < C1n * 3; i += S)  g_possum[i] = 0.f;
    for (int i = t; i < C2n * 64; i += S) g_x3[i] = NEGINF;
    for (int i = t; i < C2n; i += S)      g_batch2[i] = INT_MIN;
    for (int i = t; i < Bn * 64; i += S)  g_gsum[i] = 0.f;
    for (int i = t; i < Bn; i += S)       g_gcnt[i] = 0.f;
    if (t == 0) g_maxabs = 0.f;
}

// ---------------- K1: degree histograms (1 edge / thread) ---------------------
__global__ void k_hist(const int* __restrict__ ei, const int* __restrict__ ei2,
                       const int* __restrict__ cl1) {
    int t = blockIdx.x * blockDim.x + threadIdx.x;
    if (t < Ee) {
        atomicAdd(&g_deg1[ei[t]], 1);
        atomicAdd(&g_degD1[ei[Ee + t]], 1);
    }
    if (t < E2n) {
        atomicAdd(&g_deg2[ei2[t]], 1);
        atomicAdd(&g_degD2[ei2[E2n + t]], 1);
    }
    if (t < Nn) atomicAdd(&g_cntc1[cl1[t]], 1);
}

// ---------------- K2a/b/c: 3-phase exclusive scan ------------------------------
__device__ __forceinline__ void seg_map(int bid, int& seg, int& tile) {
    if (bid < 30)      { seg = 0; tile = bid; }
    else if (bid < 60) { seg = 1; tile = bid - 30; }
    else if (bid < 75) { seg = 2; tile = bid - 60; }
    else               { seg = 3; tile = bid - 75; }
}

__global__ void k_scanA() {
    __shared__ int wsum[8];
    int seg, tile; seg_map(blockIdx.x, seg, tile);
    const int* deg = seg == 0 ? g_deg1 : seg == 1 ? g_degD1 : seg == 2 ? g_deg2 : g_degD2;
    int* off       = seg == 0 ? g_off1 : seg == 1 ? g_offD1 : seg == 2 ? g_off2 : g_offD2;
    int n = (seg < 2) ? Nn : C1n;
    int tid = threadIdx.x, lane = tid & 31, wid = tid >> 5;
    int base = tile * 1024 + tid * 4;
    int v[4];
#pragma unroll
    for (int k = 0; k < 4; k++) v[k] = (base + k < n) ? deg[base + k] : 0;
    int s = v[0] + v[1] + v[2] + v[3];
    int incl = s;
#pragma unroll
    for (int o = 1; o < 32; o <<= 1) {
        int u = __shfl_up_sync(0xffffffffu, incl, o);
        if (lane >= o) incl += u;
    }
    if (lane == 31) wsum[wid] = incl;
    __syncthreads();
    if (tid < 8) {
        int t2 = wsum[tid];
#pragma unroll
        for (int o = 1; o < 8; o <<= 1) {
            int u = __shfl_up_sync(0xffu, t2, o);
            if (tid >= o) t2 += u;
        }
        wsum[tid] = t2;
    }
    __syncthreads();
    int run = incl - s + (wid ? wsum[wid - 1] : 0);
#pragma unroll
    for (int k = 0; k < 4; k++) {
        if (base + k < n) off[base + k] = run;
        run += v[k];
    }
    if (tid == 0) g_tsum[blockIdx.x] = wsum[7];
}

__global__ void k_scanB() {
    int tid = threadIdx.x, lane = tid & 31, w = tid >> 5;
    const int segbase[4] = {0, 30, 60, 75};
    const int segnt[4]   = {30, 30, 15, 15};
    int b = segbase[w], nt = segnt[w];
    int s = (lane < nt) ? g_tsum[b + lane] : 0;
    int incl = s;
#pragma unroll
    for (int o = 1; o < 32; o <<= 1) {
        int u = __shfl_up_sync(0xffffffffu, incl, o);
        if (lane >= o) incl += u;
    }
    if (lane < nt) g_tcar[b + lane] = incl - s;
    if (lane == 31) {
        if (w == 0) g_off1[Nn] = incl;
        else if (w == 1) g_offD1[Nn] = incl;
        else if (w == 2) g_off2[C1n] = incl;
        else g_offD2[C1n] = incl;
    }
}

__global__ void k_scanC() {
    int seg, tile; seg_map(blockIdx.x, seg, tile);
    int* off = seg == 0 ? g_off1 : seg == 1 ? g_offD1 : seg == 2 ? g_off2 : g_offD2;
    int* cur = seg == 0 ? g_cur1 : seg == 1 ? g_curD1 : seg == 2 ? g_cur2 : g_curD2;
    int n = (seg < 2) ? Nn : C1n;
    int c = g_tcar[blockIdx.x];
    int base = tile * 1024 + threadIdx.x * 4;
#pragma unroll
    for (int k = 0; k < 4; k++) {
        if (base + k < n) {
            int o = off[base + k] + c;
            off[base + k] = o;
            cur[base + k] = o;
        }
    }
}

// ---------------- K3: scatter edge ids / dst slots (1 edge / thread) ----------
__global__ void k_scat(const int* __restrict__ ei, const int* __restrict__ ei2) {
    int t = blockIdx.x * blockDim.x + threadIdx.x;
    if (t < Ee) {
        int p = atomicAdd(&g_cur1[ei[t]], 1);       g_csr1[p] = t;
        int q = atomicAdd(&g_curD1[ei[Ee + t]], 1); g_posD1[t] = q;
    }
    if (t < E2n) {
        int p = atomicAdd(&g_cur2[ei2[t]], 1);        g_csr2[p] = t;
        int q = atomicAdd(&g_curD2[ei2[E2n + t]], 1); g_posD2[t] = q;
    }
}

// ---------------- K4: conv1 by src (fused G1, warp per node) ------------------
__global__ void k_conv1(const float* __restrict__ x, const float* __restrict__ ea,
                        const int* __restrict__ ei,
                        const float* __restrict__ w1a, const float* __restrict__ b1a,
                        const float* __restrict__ w1b, const float* __restrict__ b1b) {
    __shared__ __align__(16) float w1s[4800 + 192];
    int tid = threadIdx.x;
    {
        for (int j = tid; j < 1248; j += 256) {
            float4 val;
            if (j < 1200) val = ((const float4*)w1b)[j];
            else          val = ((const float4*)b1b)[j - 1200];
            ((float4*)w1s)[j] = val;
        }
    }
    __syncthreads();
    int v = (blockIdx.x * blockDim.x + tid) >> 5;
    int lane = tid & 31;
    if (v >= Nn) return;
    float xv[6];
#pragma unroll
    for (int i = 0; i < 6; i++) xv[i] = x[v * 6 + i];
    float G[25];
#pragma unroll
    for (int r = 0; r < 25; r++) {
        float a = 0.f;
#pragma unroll
        for (int i = 0; i < 6; i++) a = fmaf(xv[i], w1s[r * 192 + i * 32 + lane], a);
        G[r] = a;
    }
    float bb = 0.f;
#pragma unroll
    for (int i = 0; i < 6; i++) bb = fmaf(xv[i], w1s[4800 + i * 32 + lane], bb);
    float wa0 = 0.f, wa1 = 0.f, wa2 = 0.f, ba = 0.f;
    if (lane < 25) { wa0 = w1a[lane]; wa1 = w1a[25 + lane]; wa2 = w1a[50 + lane]; ba = b1a[lane]; }
    int p0 = g_off1[v], p1 = g_off1[v + 1];
    for (int p = p0; p < p1; p++) {
        int e = g_csr1[p];
        int pd = g_posD1[e];
        float a0 = ea[3 * e], a1 = ea[3 * e + 1], a2 = ea[3 * e + 2];
        float h = fmaxf(fmaf(a0, wa0, fmaf(a1, wa1, fmaf(a2, wa2, ba))), 0.f);
        float msg = bb;
#pragma unroll
        for (int r = 0; r < 25; r++)
            msg = fmaf(__shfl_sync(0xffffffffu, h, r), G[r], msg);
        g_buf1[(size_t)pd * 32 + lane] = msg;
    }
}

// ---------------- K5: node1 = segment-mean(buf1) + root + elu + pool1 ---------
__global__ void k_node1(const float* __restrict__ x, const float* __restrict__ pos,
                        const int* __restrict__ batch, const int* __restrict__ cl1,
                        const float* __restrict__ root1, const float* __restrict__ bias1) {
    int n = (blockIdx.x * blockDim.x + threadIdx.x) >> 5;
    int lane = threadIdx.x & 31;
    if (n >= Nn) return;
    int p0 = g_offD1[n], p1 = g_offD1[n + 1];
    float acc = 0.f;
    for (int p = p0; p < p1; p++) acc += g_buf1[(size_t)p * 32 + lane];
    float v = acc / fmaxf((float)(p1 - p0), 1.f) + bias1[lane];
#pragma unroll
    for (int i = 0; i < 6; i++) v = fmaf(x[n * 6 + i], root1[i * 32 + lane], v);
    float x1 = elu1(v);
    int c = cl1[n];
    atomicMaxFloat(&g_xp[c * 32 + lane], x1);
    if (lane < 3) atomicAdd(&g_possum[c * 3 + lane], pos[n * 3 + lane]);
    if (lane == 0) atomicMax(&g_batchp[c], batch[n]);
}

// ---------------- K6: pool1 finalize ------------------------------------------
__global__ void k_pool1fix() {
    int c = (blockIdx.x * blockDim.x + threadIdx.x) >> 5;
    int lane = threadIdx.x & 31;
    if (c >= C1n) return;
    float v = g_xp[c * 32 + lane];
    if (v < -3e38f) g_xp[c * 32 + lane] = 0.f;
    if (lane < 3) g_possum[c * 3 + lane] = g_possum[c * 3 + lane] / fmaxf((float)g_cntc1[c], 1.f);
    if (lane == 0) g_batchp[c] = max(g_batchp[c], 0);
}

// ---------------- K7: global max |cart| ---------------------------------------
__global__ void k_maxabs(const int* __restrict__ ei2) {
    int e = blockIdx.x * blockDim.x + threadIdx.x;
    float m = 0.f;
    if (e < E2n) {
        int s = ei2[e], d = ei2[E2n + e];
#pragma unroll
        for (int k = 0; k < 3; k++)
            m = fmaxf(m, fabsf(g_possum[s * 3 + k] - g_possum[d * 3 + k]));
    }
#pragma unroll
    for (int o = 16; o; o >>= 1) m = fmaxf(m, __shfl_xor_sync(0xffffffffu, m, o));
    if ((threadIdx.x & 31) == 0) atomicMax((int*)&g_maxabs, __float_as_int(m));
}

// ---------------- K8: G2 = xp @ w2b via packed f32x2 FMA ----------------------
// grid (118, 26): x = 128-node tile, y = r-slice (25 = bias b2b).
// Output layout: column pairs (c, c+32) stored at float offsets 2c, 2c+1.
__global__ void __launch_bounds__(256) k_G2(const float* __restrict__ w2b,
                                            const float* __restrict__ b2b) {
    __shared__ __align__(16) float wsp[2048];      // [i][c][2] pairs {w[c], w[c+32]}
    __shared__ __align__(16) float2 xdup[128 * 33]; // [vv][i] duplicated {x,x}
    int tid = threadIdx.x;
    int vbase = blockIdx.x * 128;
    int rs = blockIdx.y;
    const float* wsrc = (rs < 25) ? (w2b + rs * 2048) : b2b;
    for (int j = tid; j < 2048; j += 256) {
        int i = j >> 6, col = j & 63;
        int c = col & 31, s = col >> 5;
        wsp[i * 64 + c * 2 + s] = wsrc[j];
    }
    for (int idx = tid; idx < 4096; idx += 256) {
        int vv = idx >> 5, i = idx & 31;
        float val = (vbase + vv < C1n) ? g_xp[(vbase + vv) * 32 + i] : 0.f;
        xdup[vv * 33 + i] = make_float2(val, val);
    }
    __syncthreads();
    int colg = tid & 7, nodeg = tid >> 3;
    int c4 = colg * 4;    // pair indices c4..c4+3
    int n4 = nodeg * 4;   // nodes n4..n4+3
    ull acc[4][4];
#pragma unroll
    for (int n = 0; n < 4; n++)
#pragma unroll
        for (int p = 0; p < 4; p++) acc[n][p] = 0ULL;
#pragma unroll 8
    for (int i = 0; i < 32; i++) {
        ulonglong2 wA = *(const ulonglong2*)&wsp[i * 64 + c4 * 2];
        ulonglong2 wB = *(const ulonglong2*)&wsp[i * 64 + c4 * 2 + 4];
        ull wp0 = wA.x, wp1 = wA.y, wp2 = wB.x, wp3 = wB.y;
        ull xp_[4];
#pragma unroll
        for (int n = 0; n < 4; n++)
            xp_[n] = *(const ull*)&xdup[(n4 + n) * 33 + i];
#pragma unroll
        for (int n = 0; n < 4; n++) {
            acc[n][0] = fma2(wp0, xp_[n], acc[n][0]);
            acc[n][1] = fma2(wp1, xp_[n], acc[n][1]);
            acc[n][2] = fma2(wp2, xp_[n], acc[n][2]);
            acc[n][3] = fma2(wp3, xp_[n], acc[n][3]);
        }
    }
#pragma unroll
    for (int n = 0; n < 4; n++) {
        int v = vbase + n4 + n;
        if (v < C1n) {
            float* dst = (rs < 25) ? (g_G2 + (size_t)v * 1600 + rs * 64 + c4 * 2)
                                   : (g_bb2 + v * 64 + c4 * 2);
            ulonglong2 o0; o0.x = acc[n][0]; o0.y = acc[n][1];
            ulonglong2 o1; o1.x = acc[n][2]; o1.y = acc[n][3];
            *(ulonglong2*)dst = o0;
            *(ulonglong2*)(dst + 4) = o1;
        }
    }
}

// ---------------- K9: conv2 by src (warp per C1 node, paired loads) -----------
__global__ void k_conv2(const int* __restrict__ ei2, const float* __restrict__ w2a,
                        const float* __restrict__ b2a) {
    int v = (blockIdx.x * blockDim.x + threadIdx.x) >> 5;
    int lane = threadIdx.x & 31;
    if (v >= C1n) return;
    const ull* Gp = (const ull*)(g_G2 + (size_t)v * 1600);
    float G0[25], G1[25];
#pragma unroll
    for (int r = 0; r < 25; r++) {
        ull g = Gp[r * 32 + lane];
        unpack2f(G0[r], G1[r], g);
    }
    float bb0, bb1;
    {
        ull b = ((const ull*)g_bb2)[v * 32 + lane];
        unpack2f(bb0, bb1, b);
    }
    float pv0 = g_possum[v * 3], pv1 = g_possum[v * 3 + 1], pv2 = g_possum[v * 3 + 2];
    float inv = 0.5f / g_maxabs;
    float wa0 = 0.f, wa1 = 0.f, wa2 = 0.f, ba = 0.f;
    if (lane < 25) { wa0 = w2a[lane]; wa1 = w2a[25 + lane]; wa2 = w2a[50 + lane]; ba = b2a[lane]; }
    int p0 = g_off2[v], p1 = g_off2[v + 1];
    for (int p = p0; p < p1; p++) {
        int e = g_csr2[p];
        int pd = g_posD2[e];
        int dst = ei2[E2n + e];
        float e0 = fmaf(pv0 - g_possum[dst * 3],     inv, 0.5f);
        float e1 = fmaf(pv1 - g_possum[dst * 3 + 1], inv, 0.5f);
        float e2 = fmaf(pv2 - g_possum[dst * 3 + 2], inv, 0.5f);
        float h = fmaxf(fmaf(e0, wa0, fmaf(e1, wa1, fmaf(e2, wa2, ba))), 0.f);
        float m0 = bb0, m1 = bb1;
#pragma unroll
        for (int r = 0; r < 25; r++) {
            float hr = __shfl_sync(0xffffffffu, h, r);
            m0 = fmaf(hr, G0[r], m0);
            m1 = fmaf(hr, G1[r], m1);
        }
        ((ull*)g_buf2)[(size_t)pd * 32 + lane] = pack2f(m0, m1);
    }
}

// ---------------- K10: node2 + pool2 scatter ----------------------------------
__global__ void k_node2(const int* __restrict__ cl2, const float* __restrict__ root2,
                        const float* __restrict__ bias2) {
    int c = (blockIdx.x * blockDim.x + threadIdx.x) >> 5;
    int lane = threadIdx.x & 31;
    if (c >= C1n) return;
    int p0 = g_offD2[c], p1 = g_offD2[c + 1];
    const ull ONE2 = pack2f(1.f, 1.f);
    ull accp = 0ULL;
    for (int p = p0; p < p1; p++)
        accp = fma2(((const ull*)g_buf2)[(size_t)p * 32 + lane], ONE2, accp);
    float a0, a1; unpack2f(a0, a1, accp);
    float cnt = fmaxf((float)(p1 - p0), 1.f);
    float v0 = a0 / cnt + bias2[lane];
    float v1 = a1 / cnt + bias2[lane + 32];
    float xpi = g_xp[c * 32 + lane];
#pragma unroll 8
    for (int i = 0; i < 32; i++) {
        float xi = __shfl_sync(0xffffffffu, xpi, i);
        v0 = fmaf(xi, root2[i * 64 + lane], v0);
        v1 = fmaf(xi, root2[i * 64 + lane + 32], v1);
    }
    float e0 = elu1(v0), e1 = elu1(v1);
    int c2 = cl2[c];
    atomicMaxFloat(&g_x3[c2 * 64 + lane], e0);
    atomicMaxFloat(&g_x3[c2 * 64 + lane + 32], e1);
    if (lane == 0) atomicMax(&g_batch2[c2], g_batchp[c]);
}

// ---------------- K11: pool2 finalize + global mean scatter --------------------
__global__ void k_pool2() {
    int c = (blockIdx.x * blockDim.x + threadIdx.x) >> 5;
    int lane = threadIdx.x & 31;
    if (c >= C2n) return;
    float v0 = g_x3[c * 64 + lane];      if (v0 < -3e38f) v0 = 0.f;
    float v1 = g_x3[c * 64 + lane + 32]; if (v1 < -3e38f) v1 = 0.f;
    int b = max(g_batch2[c], 0);
    atomicAdd(&g_gsum[b * 64 + lane], v0);
    atomicAdd(&g_gsum[b * 64 + lane + 32], v1);
    if (lane == 0) atomicAdd(&g_gcnt[b], 1.f);
}

// ---------------- K12: FC head + log_softmax ----------------------------------
__global__ void k_head(const float* __restrict__ fc1w, const float* __restrict__ fc1b,
                       const float* __restrict__ fc2w, const float* __restrict__ fc2b,
                       float* __restrict__ out) {
    __shared__ float g[16 * 64];
    __shared__ float hh[16 * 128];
    __shared__ float lg[16 * 10];
    int tid = threadIdx.x;
    for (int i = tid; i < 16 * 64; i += 256) g[i] = g_gsum[i] / fmaxf(g_gcnt[i >> 6], 1.f);
    __syncthreads();
    for (int o = tid; o < 16 * 128; o += 256) {
        int b = o >> 7, j = o & 127;
        float acc = fc1b[j];
        for (int k = 0; k < 64; k++) acc = fmaf(g[b * 64 + k], fc1w[k * 128 + j], acc);
        hh[o] = elu1(acc);
    }
    __syncthreads();
    if (tid < 160) {
        int b = tid / 10, k = tid % 10;
        float acc = fc2b[k];
        for (int j = 0; j < 128; j++) acc = fmaf(hh[b * 128 + j], fc2w[j * 10 + k], acc);
        lg[tid] = acc;
    }
    __syncthreads();
    if (tid < 16) {
        float m = -1e30f;
        for (int k = 0; k < 10; k++) m = fmaxf(m, lg[tid * 10 + k]);
        float s = 0.f;
        for (int k = 0; k < 10; k++) s += expf(lg[tid * 10 + k] - m);
        float ls = logf(s) + m;
        for (int k = 0; k < 10; k++) out[tid * 10 + k] = lg[tid * 10 + k] - ls;
    }
}

// ---------------- host launcher -----------------------------------------------
extern "C" void kernel_launch(void* const* d_in, const int* in_sizes, int n_in,
                              void* d_out, int out_size) {
    const float *x, *ea, *pos, *w1a, *b1a, *w1b, *b1b, *root1, *bias1;
    const float *w2a, *b2a, *w2b, *b2b, *root2, *bias2, *fc1w, *fc1b, *fc2w, *fc2b;
    const int *ei, *batch, *cl1, *ei2, *cl2;

    if (in_sizes[3] == 2 * Ee) {
        x = (const float*)d_in[0];  ea = (const float*)d_in[1];  pos = (const float*)d_in[2];
        ei = (const int*)d_in[3];   batch = (const int*)d_in[4]; cl1 = (const int*)d_in[5];
        ei2 = (const int*)d_in[6];  cl2 = (const int*)d_in[7];
        w1a = (const float*)d_in[8];  b1a = (const float*)d_in[9];
        w1b = (const float*)d_in[10]; b1b = (const float*)d_in[11];
        root1 = (const float*)d_in[12]; bias1 = (const float*)d_in[13];
        w2a = (const float*)d_in[14]; b2a = (const float*)d_in[15];
        w2b = (const float*)d_in[16]; b2b = (const float*)d_in[17];
        root2 = (const float*)d_in[18]; bias2 = (const float*)d_in[19];
        fc1w = (const float*)d_in[20]; fc1b = (const float*)d_in[21];
        fc2w = (const float*)d_in[22]; fc2b = (const float*)d_in[23];
    } else {
        x = (const float*)d_in[0];  ea = (const float*)d_in[1];  pos = (const float*)d_in[2];
        w1a = (const float*)d_in[3];  b1a = (const float*)d_in[4];
        w1b = (const float*)d_in[5];  b1b = (const float*)d_in[6];
        root1 = (const float*)d_in[7]; bias1 = (const float*)d_in[8];
        w2a = (const float*)d_in[9];  b2a = (const float*)d_in[10];
        w2b = (const float*)d_in[11]; b2b = (const float*)d_in[12];
        root2 = (const float*)d_in[13]; bias2 = (const float*)d_in[14];
        fc1w = (const float*)d_in[15]; fc1b = (const float*)d_in[16];
        fc2w = (const float*)d_in[17]; fc2b = (const float*)d_in[18];
        ei = (const int*)d_in[19];  batch = (const int*)d_in[20]; cl1 = (const int*)d_in[21];
        ei2 = (const int*)d_in[22]; cl2 = (const int*)d_in[23];
    }

    k_init<<<512, 256>>>();
    k_hist<<<(Ee + 255) / 256, 256>>>(ei, ei2, cl1);
    k_scanA<<<90, 256>>>();
    k_scanB<<<1, 128>>>();
    k_scanC<<<90, 256>>>();
    k_scat<<<(Ee + 255) / 256, 256>>>(ei, ei2);
    k_conv1<<<3750, 256>>>(x, ea, ei, w1a, b1a, w1b, b1b);
    k_node1<<<3750, 256>>>(x, pos, batch, cl1, root1, bias1);
    k_pool1fix<<<1875, 256>>>();
    k_maxabs<<<(E2n + 255) / 256, 256>>>(ei2);
    k_G2<<<dim3(118, 26), 256>>>(w2b, b2b);
    k_conv2<<<1875, 256>>>(ei2, w2a, b2a);
    k_node2<<<1875, 256>>>(cl2, root2, bias2);
    k_pool2<<<938, 256>>>();
    k_head<<<1, 256>>>(fc1w, fc1b, fc2w, fc2b, (float*)d_out);
}